// round 11
// baseline (speedup 1.0000x reference)
#include <cuda_runtime.h>

// Problem constants (fixed by setup_inputs)
#define BATCH   16
#define CHAN    4
#define H_IN    128
#define W_IN    240
#define MAXD    24
#define H_OUT   1024
#define W_OUT   1920
#define W4      (W_OUT / 4)     // 480
#define HW      (H_IN * W_IN)
#define PAD     (MAXD - 1)      // 23 zero-pad entries for negative shifts

// Low-res disparity prediction scratch (pred * 8): 16*128*240 floats ≈ 2 MB.
__device__ float g_pred[BATCH * H_IN * W_IN];

// ---------------------------------------------------------------------------
// K1: cost volume + softmax expectation. One block per (b, row-pair).
// Right row staged in smem with 23 zero-padded float4s in front, so the
// disparity loop has NO predicate / special case. Unshifted softmax
// (cost >= 0 -> exp in (0,1], no overflow).
// ---------------------------------------------------------------------------
__global__ __launch_bounds__(512) void disp_kernel(
    const float* __restrict__ fl, const float* __restrict__ fr)
{
    const int pair = blockIdx.x;         // b*64 + yp
    const int b  = pair >> 6;
    const int yp = pair & 63;
    const int half = threadIdx.x >> 8;   // row within pair
    const int x    = threadIdx.x & 255;
    const int y = yp * 2 + half;

    __shared__ float4 sr4[2][PAD + W_IN];

    // zero the pad (indices 0..22)
    if (x < PAD) sr4[half][x] = make_float4(0.f, 0.f, 0.f, 0.f);

    float4 L;
    if (x < W_IN) {
        const size_t rb = (size_t)b * (CHAN * HW) + (size_t)y * W_IN + x;
        float4 R;
        R.x = fr[rb];          R.y = fr[rb + HW];
        R.z = fr[rb + 2 * HW]; R.w = fr[rb + 3 * HW];
        sr4[half][PAD + x] = R;
        L.x = fl[rb];          L.y = fl[rb + HW];
        L.z = fl[rb + 2 * HW]; L.w = fl[rb + 3 * HW];
    }
    __syncthreads();

    if (x < W_IN) {
        const float4* __restrict__ rrow = &sr4[half][PAD + x];

        float num = 0.0f, den = 0.0f;
#pragma unroll
        for (int d = 0; d < MAXD; d++) {
            const float4 R = rrow[-d];            // pad makes this always valid
            const float c = fabsf(L.x - R.x) + fabsf(L.y - R.y)
                          + fabsf(L.z - R.z) + fabsf(L.w - R.w);
            const float e = __expf(-c);           // softmax(-cost), unshifted
            den += e;
            num += (float)d * e;
        }
        g_pred[(b * H_IN + y) * W_IN + x] = (num / den) * 8.0f;  // * 1024/128
    }

#if __CUDA_ARCH__ >= 900
    cudaTriggerProgrammaticLaunchCompletion();
#endif
}

// ---------------------------------------------------------------------------
// K2: bilinear upsample 128x240 -> 1024x1920 (align_corners).
// One thread per (b, input-row r, float4 column g). 983,040 threads.
// 480 float4/row = 15 warps exactly -> every warp store is 512B contiguous.
// PDL: all pred-independent geometry runs BEFORE cudaGridDependencySynchronize.
// ---------------------------------------------------------------------------
__global__ __launch_bounds__(256) void resize_kernel(float* __restrict__ out)
{
    const int idx = blockIdx.x * 256 + threadIdx.x;   // exact grid, no guard
    const int g = idx % W4;
    const int t = idx / W4;
    const int r = t & (H_IN - 1);
    const int b = t >> 7;

    const float xsc = 239.0f / 1919.0f;
    const float ysc = 127.0f / 1023.0f;

    // ---- hoisted x-geometry for 4 contiguous output pixels (pred-free) ----
    const int ox0 = g * 4;
    const int q = (ox0 * 239) / 1919;            // exact base input cell
    float wx[4];
    bool  hi[4];
#pragma unroll
    for (int k = 0; k < 4; k++) {
        const float xf = (float)(ox0 + k) * xsc;
        const int x0 = (int)xf;
        wx[k] = xf - (float)x0;
        hi[k] = (x0 > q);                        // pixel lies in cell q+1
    }

    const int q1 = min(q + 1, W_IN - 1);
    const int q2 = min(q + 2, W_IN - 1);
    const int r1 = min(r + 1, H_IN - 1);

    // output rows owned by input row r: floor(oy*127/1023) == r
    const int oys = (r * (H_OUT - 1) + (H_IN - 2)) / (H_IN - 1);
    const int oye = min(H_OUT - 1,
        ((r + 1) * (H_OUT - 1) + (H_IN - 2)) / (H_IN - 1) - 1);

#if __CUDA_ARCH__ >= 900
    cudaGridDependencySynchronize();             // wait for disp_kernel
#endif

    // ---- pred window (2 rows x 3 cols) into registers; clamped edges ----
    const float* __restrict__ p0r = g_pred + (b * H_IN + r)  * W_IN;
    const float* __restrict__ p1r = g_pred + (b * H_IN + r1) * W_IN;
    const float p00 = __ldg(p0r + q), p01 = __ldg(p0r + q1), p02 = __ldg(p0r + q2);
    const float D0 = __ldg(p1r + q)  - p00;
    const float D1 = __ldg(p1r + q1) - p01;
    const float D2 = __ldg(p1r + q2) - p02;

    float4* __restrict__ out4 =
        (float4*)out + (size_t)b * H_OUT * W4 + g;

    for (int oy = oys; oy <= oye; oy++) {
        const float wy = (float)oy * ysc - (float)r;
        const float v0 = p00 + wy * D0;          // y-lerp (3 FMA)
        const float v1 = p01 + wy * D1;
        const float v2 = p02 + wy * D2;
        const float d01 = v1 - v0;
        const float d12 = v2 - v1;

        float4 o;
#pragma unroll
        for (int k = 0; k < 4; k++) {
            const float base = hi[k] ? v1 : v0;
            const float del  = hi[k] ? d12 : d01;
            ((float*)&o)[k] = base + wx[k] * del;
        }
        out4[(size_t)oy * W4] = o;               // warp: 512B contiguous
    }
}

extern "C" void kernel_launch(void* const* d_in, const int* in_sizes, int n_in,
                              void* d_out, int out_size)
{
    const float* feat_l = (const float*)d_in[0];
    const float* feat_r = (const float*)d_in[1];
    float* out = (float*)d_out;

    disp_kernel<<<BATCH * (H_IN / 2), 512>>>(feat_l, feat_r);

    // Resize launched with programmatic dependent launch: its preamble
    // overlaps disp_kernel's tail; gridDependencySynchronize guards pred.
    const int total = BATCH * H_IN * W4;         // 983,040
    cudaLaunchConfig_t cfg = {};
    cfg.gridDim  = dim3(total / 256);
    cfg.blockDim = dim3(256);
    cfg.dynamicSmemBytes = 0;
    cfg.stream = 0;
    cudaLaunchAttribute attr[1];
    attr[0].id = cudaLaunchAttributeProgrammaticStreamSerialization;
    attr[0].val.programmaticStreamSerializationAllowed = 1;
    cfg.attrs = attr;
    cfg.numAttrs = 1;
    cudaLaunchKernelEx(&cfg, resize_kernel, out);
}